// round 14
// baseline (speedup 1.0000x reference)
#include <cuda_runtime.h>
#include <cstdint>

// Problem constants
#define NUM_A 8192
#define NUM_Z 8192
__device__ __constant__ float K_S = 0.05f;                   // DT/TAU
__device__ __constant__ float K_D = 1.6666666666666666e-4f;  // DT/TAU_D

#define ROWS_PER_BLOCK 4
#define TPB 256
// each thread handles 4 consecutive columns -> block covers 1024 columns

__global__ __launch_bounds__(TPB) void synapse_kernel(
    const float* __restrict__ spike,   // [NUM_A]
    const float* __restrict__ s,       // [NUM_A, NUM_Z]
    const float* __restrict__ D,       // [NUM_A, NUM_Z]
    const int*   __restrict__ syns,    // [NUM_A, NUM_Z] bool stored as 4-byte
    float*       __restrict__ s_new,   // [NUM_A, NUM_Z]
    float*       __restrict__ D_new,   // [NUM_A, NUM_Z]
    float*       __restrict__ f_all)   // [NUM_Z]
{
    const int z0 = (blockIdx.x * TPB + threadIdx.x) * 4;   // column base (4 cols/thread)
    const int a0 = blockIdx.y * ROWS_PER_BLOCK;            // row base

    float f0 = 0.f, f1 = 0.f, f2 = 0.f, f3 = 0.f;

    const float kS = K_S;
    const float kD = K_D;

    // unroll 4 is the measured optimum: ptxas keeps regs=54 and front-batches
    // the LDG.128s (DRAM ~86%). unroll 8 made it re-roll (regs 39, DRAM 72%).
    #pragma unroll 4
    for (int r = 0; r < ROWS_PER_BLOCK; ++r) {
        const int a = a0 + r;
        const float spk = __ldg(&spike[a]);
        const size_t idx = (size_t)a * NUM_Z + (size_t)z0;

        const float4 sv = *reinterpret_cast<const float4*>(s + idx);
        const float4 Dv = *reinterpret_cast<const float4*>(D + idx);
        const int4   mv = *reinterpret_cast<const int4*>(syns + idx);

        // false is all-zero bits in both int32 and float32 encodings.
        const float m0 = (mv.x != 0) ? 1.0f : 0.0f;
        const float m1 = (mv.y != 0) ? 1.0f : 0.0f;
        const float m2 = (mv.z != 0) ? 1.0f : 0.0f;
        const float m3 = (mv.w != 0) ? 1.0f : 0.0f;

        // s_new = s + m * (spk - s*(DT/TAU))
        float4 sn;
        sn.x = sv.x + m0 * (spk - sv.x * kS);
        sn.y = sv.y + m1 * (spk - sv.y * kS);
        sn.z = sv.z + m2 * (spk - sv.z * kS);
        sn.w = sv.w + m3 * (spk - sv.w * kS);

        // D_new = D + m * ((1 - D) * (DT/TAU_D))   (P_D == 0)
        float4 Dn;
        Dn.x = Dv.x + m0 * ((1.0f - Dv.x) * kD);
        Dn.y = Dv.y + m1 * ((1.0f - Dv.y) * kD);
        Dn.z = Dv.z + m2 * ((1.0f - Dv.z) * kD);
        Dn.w = Dv.w + m3 * ((1.0f - Dv.w) * kD);

        // f += m * D_new * s_new
        f0 += m0 * Dn.x * sn.x;
        f1 += m1 * Dn.y * sn.y;
        f2 += m2 * Dn.z * sn.z;
        f3 += m3 * Dn.w * sn.w;

        *reinterpret_cast<float4*>(s_new + idx) = sn;
        *reinterpret_cast<float4*>(D_new + idx) = Dn;
    }

    atomicAdd(&f_all[z0 + 0], f0);
    atomicAdd(&f_all[z0 + 1], f1);
    atomicAdd(&f_all[z0 + 2], f2);
    atomicAdd(&f_all[z0 + 3], f3);
}

extern "C" void kernel_launch(void* const* d_in, const int* in_sizes, int n_in,
                              void* d_out, int out_size) {
    const float* spike = (const float*)d_in[0];
    const float* s     = (const float*)d_in[1];
    const float* D     = (const float*)d_in[2];
    const int*   syns  = (const int*)d_in[3];

    float* out   = (float*)d_out;
    float* s_new = out;
    float* D_new = out + (size_t)NUM_A * NUM_Z;
    float* f_all = out + 2 * (size_t)NUM_A * NUM_Z;

    // Zero f_all (accumulated via atomics; d_out is poisoned).
    cudaMemsetAsync(f_all, 0, NUM_Z * sizeof(float));

    dim3 grid(NUM_Z / (TPB * 4), NUM_A / ROWS_PER_BLOCK);  // (8, 2048) = 16384 CTAs
    synapse_kernel<<<grid, TPB>>>(spike, s, D, syns, s_new, D_new, f_all);
}

// round 15
// speedup vs baseline: 1.0309x; 1.0309x over previous
#include <cuda_runtime.h>
#include <cstdint>

// Problem constants
#define NUM_A 8192
#define NUM_Z 8192
__device__ __constant__ float K_S = 0.05f;                   // DT/TAU
__device__ __constant__ float K_D = 1.6666666666666666e-4f;  // DT/TAU_D

#define ROWS_PER_BLOCK 8
#define TPB 256
// each thread handles 4 consecutive columns -> block covers 1024 columns

__global__ __launch_bounds__(TPB) void synapse_kernel(
    const float* __restrict__ spike,   // [NUM_A]
    const float* __restrict__ s,       // [NUM_A, NUM_Z]
    const float* __restrict__ D,       // [NUM_A, NUM_Z]
    const int*   __restrict__ syns,    // [NUM_A, NUM_Z] bool stored as 4-byte
    float*       __restrict__ s_new,   // [NUM_A, NUM_Z]
    float*       __restrict__ D_new,   // [NUM_A, NUM_Z]
    float*       __restrict__ f_all)   // [NUM_Z]
{
    const int z0 = (blockIdx.x * TPB + threadIdx.x) * 4;   // column base (4 cols/thread)
    const int a0 = blockIdx.y * ROWS_PER_BLOCK;            // row base

    float f0 = 0.f, f1 = 0.f, f2 = 0.f, f3 = 0.f;

    const float kS = K_S;
    const float kD = K_D;

    // unroll 4 with 8 loop trips is the measured optimum: ptxas keeps regs=54
    // and front-batches the LDG.128s (DRAM ~86%, profiled 190.5us).
    // unroll 8 re-rolled (regs 39, DRAM 72%); RPB=4 collapsed the loop and
    // also broke the schedule (regs 42, DRAM 70%). Do not perturb this body.
    #pragma unroll 4
    for (int r = 0; r < ROWS_PER_BLOCK; ++r) {
        const int a = a0 + r;
        const float spk = __ldg(&spike[a]);
        const size_t idx = (size_t)a * NUM_Z + (size_t)z0;

        const float4 sv = *reinterpret_cast<const float4*>(s + idx);
        const float4 Dv = *reinterpret_cast<const float4*>(D + idx);
        const int4   mv = *reinterpret_cast<const int4*>(syns + idx);

        // false is all-zero bits in both int32 and float32 encodings.
        const float m0 = (mv.x != 0) ? 1.0f : 0.0f;
        const float m1 = (mv.y != 0) ? 1.0f : 0.0f;
        const float m2 = (mv.z != 0) ? 1.0f : 0.0f;
        const float m3 = (mv.w != 0) ? 1.0f : 0.0f;

        // s_new = s + m * (spk - s*(DT/TAU))
        float4 sn;
        sn.x = sv.x + m0 * (spk - sv.x * kS);
        sn.y = sv.y + m1 * (spk - sv.y * kS);
        sn.z = sv.z + m2 * (spk - sv.z * kS);
        sn.w = sv.w + m3 * (spk - sv.w * kS);

        // D_new = D + m * ((1 - D) * (DT/TAU_D))   (P_D == 0)
        float4 Dn;
        Dn.x = Dv.x + m0 * ((1.0f - Dv.x) * kD);
        Dn.y = Dv.y + m1 * ((1.0f - Dv.y) * kD);
        Dn.z = Dv.z + m2 * ((1.0f - Dv.z) * kD);
        Dn.w = Dv.w + m3 * ((1.0f - Dv.w) * kD);

        // f += m * D_new * s_new
        f0 += m0 * Dn.x * sn.x;
        f1 += m1 * Dn.y * sn.y;
        f2 += m2 * Dn.z * sn.z;
        f3 += m3 * Dn.w * sn.w;

        *reinterpret_cast<float4*>(s_new + idx) = sn;
        *reinterpret_cast<float4*>(D_new + idx) = Dn;
    }

    atomicAdd(&f_all[z0 + 0], f0);
    atomicAdd(&f_all[z0 + 1], f1);
    atomicAdd(&f_all[z0 + 2], f2);
    atomicAdd(&f_all[z0 + 3], f3);
}

extern "C" void kernel_launch(void* const* d_in, const int* in_sizes, int n_in,
                              void* d_out, int out_size) {
    const float* spike = (const float*)d_in[0];
    const float* s     = (const float*)d_in[1];
    const float* D     = (const float*)d_in[2];
    const int*   syns  = (const int*)d_in[3];

    float* out   = (float*)d_out;
    float* s_new = out;
    float* D_new = out + (size_t)NUM_A * NUM_Z;
    float* f_all = out + 2 * (size_t)NUM_A * NUM_Z;

    // Zero f_all (accumulated via atomics; d_out is poisoned).
    cudaMemsetAsync(f_all, 0, NUM_Z * sizeof(float));

    dim3 grid(NUM_Z / (TPB * 4), NUM_A / ROWS_PER_BLOCK);  // (8, 1024) = 8192 CTAs
    synapse_kernel<<<grid, TPB>>>(spike, s, D, syns, s_new, D_new, f_all);
}

// round 16
// speedup vs baseline: 1.0316x; 1.0006x over previous
#include <cuda_runtime.h>
#include <cstdint>

// Problem constants
#define NUM_A 8192
#define NUM_Z 8192
__device__ __constant__ float K_S = 0.05f;                   // DT/TAU
__device__ __constant__ float K_D = 1.6666666666666666e-4f;  // DT/TAU_D

#define ROWS_PER_BLOCK 8
#define TPB 128
// each thread handles 4 consecutive columns -> block covers 512 columns

__global__ __launch_bounds__(TPB) void synapse_kernel(
    const float* __restrict__ spike,   // [NUM_A]
    const float* __restrict__ s,       // [NUM_A, NUM_Z]
    const float* __restrict__ D,       // [NUM_A, NUM_Z]
    const int*   __restrict__ syns,    // [NUM_A, NUM_Z] bool stored as 4-byte
    float*       __restrict__ s_new,   // [NUM_A, NUM_Z]
    float*       __restrict__ D_new,   // [NUM_A, NUM_Z]
    float*       __restrict__ f_all)   // [NUM_Z]
{
    const int z0 = (blockIdx.x * TPB + threadIdx.x) * 4;   // column base (4 cols/thread)
    const int a0 = blockIdx.y * ROWS_PER_BLOCK;            // row base

    float f0 = 0.f, f1 = 0.f, f2 = 0.f, f3 = 0.f;

    const float kS = K_S;
    const float kD = K_D;

    // unroll 4 with 8 loop trips is the measured optimum: ptxas keeps regs=54
    // and front-batches the LDG.128s (DRAM ~86%, profiled 190.5us).
    // unroll 8 re-rolled (regs 39); RPB=4 collapsed the loop (regs 42).
    // Do not perturb this body.
    #pragma unroll 4
    for (int r = 0; r < ROWS_PER_BLOCK; ++r) {
        const int a = a0 + r;
        const float spk = __ldg(&spike[a]);
        const size_t idx = (size_t)a * NUM_Z + (size_t)z0;

        const float4 sv = *reinterpret_cast<const float4*>(s + idx);
        const float4 Dv = *reinterpret_cast<const float4*>(D + idx);
        const int4   mv = *reinterpret_cast<const int4*>(syns + idx);

        // false is all-zero bits in both int32 and float32 encodings.
        const float m0 = (mv.x != 0) ? 1.0f : 0.0f;
        const float m1 = (mv.y != 0) ? 1.0f : 0.0f;
        const float m2 = (mv.z != 0) ? 1.0f : 0.0f;
        const float m3 = (mv.w != 0) ? 1.0f : 0.0f;

        // s_new = s + m * (spk - s*(DT/TAU))
        float4 sn;
        sn.x = sv.x + m0 * (spk - sv.x * kS);
        sn.y = sv.y + m1 * (spk - sv.y * kS);
        sn.z = sv.z + m2 * (spk - sv.z * kS);
        sn.w = sv.w + m3 * (spk - sv.w * kS);

        // D_new = D + m * ((1 - D) * (DT/TAU_D))   (P_D == 0)
        float4 Dn;
        Dn.x = Dv.x + m0 * ((1.0f - Dv.x) * kD);
        Dn.y = Dv.y + m1 * ((1.0f - Dv.y) * kD);
        Dn.z = Dv.z + m2 * ((1.0f - Dv.z) * kD);
        Dn.w = Dv.w + m3 * ((1.0f - Dv.w) * kD);

        // f += m * D_new * s_new
        f0 += m0 * Dn.x * sn.x;
        f1 += m1 * Dn.y * sn.y;
        f2 += m2 * Dn.z * sn.z;
        f3 += m3 * Dn.w * sn.w;

        *reinterpret_cast<float4*>(s_new + idx) = sn;
        *reinterpret_cast<float4*>(D_new + idx) = Dn;
    }

    atomicAdd(&f_all[z0 + 0], f0);
    atomicAdd(&f_all[z0 + 1], f1);
    atomicAdd(&f_all[z0 + 2], f2);
    atomicAdd(&f_all[z0 + 3], f3);
}

extern "C" void kernel_launch(void* const* d_in, const int* in_sizes, int n_in,
                              void* d_out, int out_size) {
    const float* spike = (const float*)d_in[0];
    const float* s     = (const float*)d_in[1];
    const float* D     = (const float*)d_in[2];
    const int*   syns  = (const int*)d_in[3];

    float* out   = (float*)d_out;
    float* s_new = out;
    float* D_new = out + (size_t)NUM_A * NUM_Z;
    float* f_all = out + 2 * (size_t)NUM_A * NUM_Z;

    // Zero f_all (accumulated via atomics; d_out is poisoned).
    cudaMemsetAsync(f_all, 0, NUM_Z * sizeof(float));

    dim3 grid(NUM_Z / (TPB * 4), NUM_A / ROWS_PER_BLOCK);  // (16, 1024) = 16384 CTAs
    synapse_kernel<<<grid, TPB>>>(spike, s, D, syns, s_new, D_new, f_all);
}

// round 17
// speedup vs baseline: 1.0383x; 1.0065x over previous
#include <cuda_runtime.h>
#include <cstdint>

// Problem constants
#define NUM_A 8192
#define NUM_Z 8192
__device__ __constant__ float K_S = 0.05f;                   // DT/TAU
__device__ __constant__ float K_D = 1.6666666666666666e-4f;  // DT/TAU_D

#define ROWS_PER_BLOCK 8
#define TPB 256
// each thread handles 4 consecutive columns -> block covers 1024 columns

__global__ __launch_bounds__(TPB) void synapse_kernel(
    const float* __restrict__ spike,   // [NUM_A]
    const float* __restrict__ s,       // [NUM_A, NUM_Z]
    const float* __restrict__ D,       // [NUM_A, NUM_Z]
    const int*   __restrict__ syns,    // [NUM_A, NUM_Z] bool stored as 4-byte
    float*       __restrict__ s_new,   // [NUM_A, NUM_Z]
    float*       __restrict__ D_new,   // [NUM_A, NUM_Z]
    float*       __restrict__ f_all)   // [NUM_Z]
{
    const int z0 = (blockIdx.x * TPB + threadIdx.x) * 4;   // column base (4 cols/thread)
    const int a0 = blockIdx.y * ROWS_PER_BLOCK;            // row base

    float f0 = 0.f, f1 = 0.f, f2 = 0.f, f3 = 0.f;

    const float kS = K_S;
    const float kD = K_D;

    // unroll 4 with 8 loop trips is the measured optimum: ptxas keeps regs=54
    // and front-batches the LDG.128s (DRAM ~86%, profiled 190.5us).
    // unroll 8 re-rolled (regs 39, DRAM 72%); RPB=4 collapsed the loop and
    // also broke the schedule (regs 42, DRAM 70%). Do not perturb this body.
    #pragma unroll 4
    for (int r = 0; r < ROWS_PER_BLOCK; ++r) {
        const int a = a0 + r;
        const float spk = __ldg(&spike[a]);
        const size_t idx = (size_t)a * NUM_Z + (size_t)z0;

        const float4 sv = *reinterpret_cast<const float4*>(s + idx);
        const float4 Dv = *reinterpret_cast<const float4*>(D + idx);
        const int4   mv = *reinterpret_cast<const int4*>(syns + idx);

        // false is all-zero bits in both int32 and float32 encodings.
        const float m0 = (mv.x != 0) ? 1.0f : 0.0f;
        const float m1 = (mv.y != 0) ? 1.0f : 0.0f;
        const float m2 = (mv.z != 0) ? 1.0f : 0.0f;
        const float m3 = (mv.w != 0) ? 1.0f : 0.0f;

        // s_new = s + m * (spk - s*(DT/TAU))
        float4 sn;
        sn.x = sv.x + m0 * (spk - sv.x * kS);
        sn.y = sv.y + m1 * (spk - sv.y * kS);
        sn.z = sv.z + m2 * (spk - sv.z * kS);
        sn.w = sv.w + m3 * (spk - sv.w * kS);

        // D_new = D + m * ((1 - D) * (DT/TAU_D))   (P_D == 0)
        float4 Dn;
        Dn.x = Dv.x + m0 * ((1.0f - Dv.x) * kD);
        Dn.y = Dv.y + m1 * ((1.0f - Dv.y) * kD);
        Dn.z = Dv.z + m2 * ((1.0f - Dv.z) * kD);
        Dn.w = Dv.w + m3 * ((1.0f - Dv.w) * kD);

        // f += m * D_new * s_new
        f0 += m0 * Dn.x * sn.x;
        f1 += m1 * Dn.y * sn.y;
        f2 += m2 * Dn.z * sn.z;
        f3 += m3 * Dn.w * sn.w;

        *reinterpret_cast<float4*>(s_new + idx) = sn;
        *reinterpret_cast<float4*>(D_new + idx) = Dn;
    }

    atomicAdd(&f_all[z0 + 0], f0);
    atomicAdd(&f_all[z0 + 1], f1);
    atomicAdd(&f_all[z0 + 2], f2);
    atomicAdd(&f_all[z0 + 3], f3);
}

extern "C" void kernel_launch(void* const* d_in, const int* in_sizes, int n_in,
                              void* d_out, int out_size) {
    const float* spike = (const float*)d_in[0];
    const float* s     = (const float*)d_in[1];
    const float* D     = (const float*)d_in[2];
    const int*   syns  = (const int*)d_in[3];

    float* out   = (float*)d_out;
    float* s_new = out;
    float* D_new = out + (size_t)NUM_A * NUM_Z;
    float* f_all = out + 2 * (size_t)NUM_A * NUM_Z;

    // Zero f_all (accumulated via atomics; d_out is poisoned).
    cudaMemsetAsync(f_all, 0, NUM_Z * sizeof(float));

    dim3 grid(NUM_Z / (TPB * 4), NUM_A / ROWS_PER_BLOCK);  // (8, 1024) = 8192 CTAs
    synapse_kernel<<<grid, TPB>>>(spike, s, D, syns, s_new, D_new, f_all);
}